// round 15
// baseline (speedup 1.0000x reference)
#include <cuda_runtime.h>
#include <cuda_fp16.h>
#include <cstdint>

// SoftmaxSelfAttention B=2,H=16,S=2048,D=64 fp32.
// Round 15: PERSISTENT fp16 HMMA flash attention + split-KV(2).
// grid=444 (=148 SMs x 3 CTAs); each CTA processes units {bid, bid+444,
// bid+888}. The cp.async pipeline continues ACROSS units (last tile of unit
// u prefetches tile 0 of unit u+444) so the ~7us pipeline-refill prologue is
// paid once, not once per wave. Q fragments loaded directly from gmem (no
// smem staging / syncs). Inner loop identical to R13 (best: 111.4us).

#define SEQi  2048
#define Dhi   64
#define TMi   128
#define TNi   128
#define NTH   8                           // tiles per kv half
#define UNITS 1024                        // 16 qt x 32 bh x 2 kvh
#define USTRIDE 444
#define PADHi 72
#define ROWBi 144
#define TILEBi (TNi * ROWBi)              // 18432 B
#define NELEMi ((size_t)32 * SEQi * Dhi)
#define POELEM ((size_t)32 * 16 * TMi * Dhi)   // partial O elems per half

__device__ __align__(16) __half gKh[NELEMi];
__device__ __align__(16) __half gVh[NELEMi];
__device__ __align__(16) float gPO[2][POELEM];
__device__ __align__(16) float gPL[2][32 * 16 * TMi];

namespace {
constexpr int SM_BUF   = 2048;
constexpr int STAGEB   = 2 * TILEBi;
constexpr int SM_TOTAL = SM_BUF + 2 * STAGEB;   // 75776 B -> 3 CTAs/SM
constexpr float SCL = 0.18033688011112042f;     // log2(e)/8
constexpr float L2E = 1.4426950408889634f;
}

__device__ __forceinline__ uint32_t s2u(const void* p) {
    uint32_t a;
    asm("{ .reg .u64 t; cvta.to.shared.u64 t, %1; cvt.u32.u64 %0, t; }" : "=r"(a) : "l"(p));
    return a;
}
__device__ __forceinline__ void ldx4(uint32_t r[4], uint32_t a) {
    asm volatile("ldmatrix.sync.aligned.m8n8.x4.shared.b16 {%0,%1,%2,%3}, [%4];"
                 : "=r"(r[0]), "=r"(r[1]), "=r"(r[2]), "=r"(r[3]) : "r"(a));
}
__device__ __forceinline__ void ldx4t(uint32_t r[4], uint32_t a) {
    asm volatile("ldmatrix.sync.aligned.m8n8.x4.trans.shared.b16 {%0,%1,%2,%3}, [%4];"
                 : "=r"(r[0]), "=r"(r[1]), "=r"(r[2]), "=r"(r[3]) : "r"(a));
}
__device__ __forceinline__ void mma16816(float c[4], const uint32_t a[4],
                                         uint32_t b0, uint32_t b1) {
    asm("mma.sync.aligned.m16n8k16.row.col.f32.f16.f16.f32 "
        "{%0,%1,%2,%3}, {%4,%5,%6,%7}, {%8,%9}, {%0,%1,%2,%3};"
        : "+f"(c[0]), "+f"(c[1]), "+f"(c[2]), "+f"(c[3])
        : "r"(a[0]), "r"(a[1]), "r"(a[2]), "r"(a[3]), "r"(b0), "r"(b1));
}
__device__ __forceinline__ uint32_t pack2h(float a, float b) {
    uint32_t h;
    asm("cvt.rn.f16x2.f32 %0, %1, %2;" : "=r"(h) : "f"(b), "f"(a));
    return h;
}
__device__ __forceinline__ uint32_t h2ex2(uint32_t x) {
    uint32_t r;
    asm("ex2.approx.f16x2 %0, %1;" : "=r"(r) : "r"(x));
    return r;
}

// ---------------- pre-pass: fp32 K/V -> fp16 scratch ----------------
__global__ __launch_bounds__(256)
void conv_kernel(const float* __restrict__ K, const float* __restrict__ V)
{
    size_t base = (size_t)blockIdx.x * 1024 + threadIdx.x;   // float4 index
    const float* src = blockIdx.y ? V : K;
    __half* dst = blockIdx.y ? gVh : gKh;
    float4 x[4];
    #pragma unroll
    for (int i = 0; i < 4; i++) x[i] = __ldg((const float4*)src + base + i * 256);
    #pragma unroll
    for (int i = 0; i < 4; i++) {
        size_t e = base + i * 256;
        *(uint2*)(dst + e * 4) = make_uint2(pack2h(x[i].x, x[i].y), pack2h(x[i].z, x[i].w));
    }
}

__device__ __forceinline__ void prefetch_tile(uint32_t sdst, const __half* gsrc, int tid)
{
    #pragma unroll
    for (int j = 0; j < 8; j++) {
        int chunk = tid + j * 128;
        int row = chunk >> 3, c8 = chunk & 7;
        uint32_t d = sdst + (uint32_t)(row * ROWBi + c8 * 16);
        unsigned long long s =
            (unsigned long long)__cvta_generic_to_global(gsrc + (size_t)row * Dhi + c8 * 8);
        asm volatile("cp.async.cg.shared.global [%0], [%1], 16;" :: "r"(d), "l"(s));
    }
}

// ---- pipeline stages (R13 inner loop, unchanged) ----
__device__ __forceinline__ void qk_block(const uint32_t qf[2][4][4], uint32_t sKh,
                                         int pair, int lid, float sraw[2][2][4])
{
    #pragma unroll
    for (int half = 0; half < 2; half++) {
        int key = pair * 16 + half * 8 + (lid & 7);
        uint32_t off = (uint32_t)(key * PADHi + ((lid >> 3) << 3)) * 2;
        uint32_t kh8[8];
        ldx4(&kh8[0], sKh + off);
        ldx4(&kh8[4], sKh + off + 64);
        #pragma unroll
        for (int rg = 0; rg < 2; rg++) {
            float acc[4] = {0.f, 0.f, 0.f, 0.f};
            #pragma unroll
            for (int j = 0; j < 4; j++)
                mma16816(acc, qf[rg][j], kh8[2 * j], kh8[2 * j + 1]);
            #pragma unroll
            for (int c = 0; c < 4; c++) sraw[rg][half][c] = acc[c];
        }
    }
}

__device__ __forceinline__ void softmax_pack(const float sraw[2][2][4],
                                             const float* biasT, int pair, int lid,
                                             uint32_t ap[2][4])
{
    #pragma unroll
    for (int half = 0; half < 2; half++) {
        float b0 = biasT[pair * 16 + half * 8 + 2 * (lid & 3)];
        float b1 = biasT[pair * 16 + half * 8 + 2 * (lid & 3) + 1];
        #pragma unroll
        for (int rg = 0; rg < 2; rg++) {
            float s0 = fmaf(sraw[rg][half][0], SCL, b0);
            float s1 = fmaf(sraw[rg][half][1], SCL, b1);
            float s2 = fmaf(sraw[rg][half][2], SCL, b0);
            float s3 = fmaf(sraw[rg][half][3], SCL, b1);
            ap[rg][half * 2]     = h2ex2(pack2h(s0, s1));
            ap[rg][half * 2 + 1] = h2ex2(pack2h(s2, s3));
        }
    }
}

__device__ __forceinline__ void pv_block(const uint32_t ap[2][4], uint32_t sVh,
                                         int pair, int lid, float o[2][8][4],
                                         float ox[2][4], uint32_t onesb)
{
    mma16816(ox[0], ap[0], onesb, onesb);
    mma16816(ox[1], ap[1], onesb, onesb);
    int keyr = pair * 16 + (lid & 15);
    #pragma unroll
    for (int np = 0; np < 4; np++) {
        uint32_t off = (uint32_t)(keyr * PADHi + np * 16 + ((lid >> 4) << 3)) * 2;
        uint32_t vh[4];
        ldx4t(vh, sVh + off);
        #pragma unroll
        for (int rg = 0; rg < 2; rg++) {
            mma16816(o[rg][2 * np],     ap[rg], vh[0], vh[1]);
            mma16816(o[rg][2 * np + 1], ap[rg], vh[2], vh[3]);
        }
    }
}

// direct-from-gmem Q fragment load (m16n8k16 A layout), fp32 -> fp16 pack
__device__ __forceinline__ void load_qf(const float* __restrict__ Qb,
                                        int wid, int lid, uint32_t qf[2][4][4])
{
    int r = lid >> 2, c = 2 * (lid & 3);
    #pragma unroll
    for (int rg = 0; rg < 2; rg++) {
        int R = wid * 32 + rg * 16 + r;
        #pragma unroll
        for (int j = 0; j < 4; j++) {
            const float* p = Qb + (size_t)R * Dhi + 16 * j + c;
            float2 x0 = __ldg((const float2*)p);
            float2 x1 = __ldg((const float2*)(p + 8 * Dhi));
            float2 x2 = __ldg((const float2*)(p + 8));
            float2 x3 = __ldg((const float2*)(p + 8 * Dhi + 8));
            qf[rg][j][0] = pack2h(x0.x, x0.y);
            qf[rg][j][1] = pack2h(x1.x, x1.y);
            qf[rg][j][2] = pack2h(x2.x, x2.y);
            qf[rg][j][3] = pack2h(x3.x, x3.y);
        }
    }
}

__global__ __launch_bounds__(128, 3)
void fa_hmma_kernel(const float* __restrict__ Q, const float* __restrict__ Mk)
{
    extern __shared__ char sm[];
    float* biasB = (float*)sm;
    const uint32_t sb = s2u(sm);
    const uint32_t sK[2] = {sb + SM_BUF, sb + SM_BUF + STAGEB};
    const uint32_t sV[2] = {sK[0] + TILEBi, sK[1] + TILEBi};

    const int tid = threadIdx.x, wid = tid >> 5, lid = tid & 31;
    const uint32_t onesb = (lid < 4) ? 0x3C003C00u : 0u;

    int u = blockIdx.x;                    // first work unit (< 444 < UNITS)
    // decode unit -> (qt, bh, kvh)
    int kvh = u & 1, bh = (u >> 1) & 31, qt = u >> 6;
    const float* Qb = Q + ((size_t)bh * SEQi + (size_t)qt * TMi) * Dhi;
    const float* mb = Mk + (size_t)(bh >> 4) * SEQi + (size_t)kvh * (NTH * TNi);
    size_t kbase = (size_t)bh * SEQi * Dhi + (size_t)kvh * (NTH * TNi) * Dhi;

    // prime the pipeline: tile 0 of unit u, bias slice 0
    prefetch_tile(sK[0], gKh + kbase, tid);
    prefetch_tile(sV[0], gVh + kbase, tid);
    asm volatile("cp.async.commit_group;" ::: "memory");
    biasB[tid] = -1.0e6f * (1.0f - __ldg(&mb[tid])) * L2E;

    uint32_t qf[2][4][4];
    load_qf(Qb, wid, lid, qf);

    int stg = 0;
    for (;;) {
        float o[2][8][4];
        float ox[2][4];
        #pragma unroll
        for (int rg = 0; rg < 2; rg++) {
            #pragma unroll
            for (int i = 0; i < 8; i++)
                #pragma unroll
                for (int j = 0; j < 4; j++) o[rg][i][j] = 0.0f;
            #pragma unroll
            for (int j = 0; j < 4; j++) ox[rg][j] = 0.0f;
        }

        const int nu = u + USTRIDE;        // next unit (if any)

        for (int kt = 0; kt < NTH; kt++) {
            asm volatile("cp.async.wait_group 0;" ::: "memory");
            __syncthreads();   // tile kt resident in stage stg; stg^1 free

            if (kt + 1 < NTH) {            // prefetch this unit's next tile
                const size_t tb = kbase + (size_t)(kt + 1) * TNi * Dhi;
                prefetch_tile(sK[stg ^ 1], gKh + tb, tid);
                prefetch_tile(sV[stg ^ 1], gVh + tb, tid);
                asm volatile("cp.async.commit_group;" ::: "memory");
                biasB[(stg ^ 1) * 128 + tid] =
                    -1.0e6f * (1.0f - __ldg(&mb[(kt + 1) * TNi + tid])) * L2E;
            } else if (nu < UNITS) {       // prefetch NEXT UNIT's tile 0
                int kvh2 = nu & 1, bh2 = (nu >> 1) & 31;
                size_t kb2 = (size_t)bh2 * SEQi * Dhi + (size_t)kvh2 * (NTH * TNi) * Dhi;
                const float* mb2 = Mk + (size_t)(bh2 >> 4) * SEQi + (size_t)kvh2 * (NTH * TNi);
                prefetch_tile(sK[stg ^ 1], gKh + kb2, tid);
                prefetch_tile(sV[stg ^ 1], gVh + kb2, tid);
                asm volatile("cp.async.commit_group;" ::: "memory");
                biasB[(stg ^ 1) * 128 + tid] = -1.0e6f * (1.0f - __ldg(&mb2[tid])) * L2E;
            }

            const uint32_t sKh = sK[stg], sVh = sV[stg];
            const float* biasT = biasB + stg * 128;

            // ---- software-pipelined pair loop: QK(p+1) || PV(p) ----
            uint32_t ap[2][4];
            {
                float sraw[2][2][4];
                qk_block(qf, sKh, 0, lid, sraw);
                softmax_pack(sraw, biasT, 0, lid, ap);
            }
            #pragma unroll
            for (int p = 0; p < 8; p++) {
                float sn[2][2][4];
                if (p < 7) qk_block(qf, sKh, p + 1, lid, sn);
                pv_block(ap, sVh, p, lid, o, ox, onesb);
                if (p < 7) softmax_pack(sn, biasT, p + 1, lid, ap);
            }
            stg ^= 1;
        }

        // ---- epilogue: unnormalized partial O + row sums (gmem only) ----
        float* pO = gPO[kvh] + ((size_t)bh * 16 + qt) * (TMi * Dhi);
        float* pL = gPL[kvh] + ((size_t)bh * 16 + qt) * TMi;
        #pragma unroll
        for (int rg = 0; rg < 2; rg++) {
            int row0 = wid * 32 + rg * 16 + (lid >> 2);
            int col  = 2 * (lid & 3);
            if ((lid & 3) == 0) {
                pL[row0]     = ox[rg][0];
                pL[row0 + 8] = ox[rg][2];
            }
            #pragma unroll
            for (int nt = 0; nt < 8; nt++) {
                int c = nt * 8 + col;
                *(float2*)(pO + (size_t)row0 * Dhi + c) =
                    make_float2(o[rg][nt][0], o[rg][nt][1]);
                *(float2*)(pO + (size_t)(row0 + 8) * Dhi + c) =
                    make_float2(o[rg][nt][2], o[rg][nt][3]);
            }
        }

        if (nu >= UNITS) break;
        // advance to next unit; its tile 0 is already in flight
        u = nu;
        kvh = u & 1; bh = (u >> 1) & 31; qt = u >> 6;
        Qb = Q + ((size_t)bh * SEQi + (size_t)qt * TMi) * Dhi;
        mb = Mk + (size_t)(bh >> 4) * SEQi + (size_t)kvh * (NTH * TNi);
        kbase = (size_t)bh * SEQi * Dhi + (size_t)kvh * (NTH * TNi) * Dhi;
        load_qf(Qb, wid, lid, qf);
    }
}

// ---------------- merge: O = (p0 + p1) / (l0 + l1) ----------------
__global__ __launch_bounds__(256)
void merge_kernel(float* __restrict__ O)
{
    size_t base = (size_t)blockIdx.x * 512 + threadIdx.x;
    #pragma unroll
    for (int i = 0; i < 2; i++) {
        size_t e4 = base + i * 256;
        size_t e  = e4 * 4;
        size_t row = e >> 6;
        float inv = 1.0f / (gPL[0][row] + gPL[1][row]);
        float4 a = *(const float4*)(gPO[0] + e);
        float4 b = *(const float4*)(gPO[1] + e);
        float4 r;
        r.x = (a.x + b.x) * inv;
        r.y = (a.y + b.y) * inv;
        r.z = (a.z + b.z) * inv;
        r.w = (a.w + b.w) * inv;
        *(float4*)(O + e) = r;
    }
}

extern "C" void kernel_launch(void* const* d_in, const int* in_sizes, int n_in,
                              void* d_out, int out_size)
{
    const float* Q = (const float*)d_in[0];
    const float* K = (const float*)d_in[1];
    const float* V = (const float*)d_in[2];
    const float* M = (const float*)d_in[3];
    float* O = (float*)d_out;

    conv_kernel<<<dim3(1024, 2), 256>>>(K, V);

    cudaFuncSetAttribute(fa_hmma_kernel,
                         cudaFuncAttributeMaxDynamicSharedMemorySize, SM_TOTAL);
    fa_hmma_kernel<<<USTRIDE, 128, SM_TOTAL>>>(Q, M);   // persistent: 444 CTAs

    merge_kernel<<<(unsigned)(POELEM / 4 / 512), 256>>>(O);
}

// round 16
// speedup vs baseline: 1.1018x; 1.1018x over previous
#include <cuda_runtime.h>
#include <cuda_fp16.h>
#include <cstdint>

// SoftmaxSelfAttention B=2,H=16,S=2048,D=64 fp32.
// Round 16: R13 inner loop (best: 111.4us) + INLINE MERGE: split-KV(2)
// partials are combined by the second-finishing CTA of each (bh,qt) pair
// (threadfence + atomic counter), overlapping merge with the main kernel's
// tail and removing the separate merge launch. Deterministic: sums always
// computed in fixed kvh order.

#define SEQi  2048
#define Dhi   64
#define TMi   128
#define TNi   128
#define NTH   8                           // tiles per kv half
#define PADHi 72
#define ROWBi 144
#define TILEBi (TNi * ROWBi)              // 18432 B
#define NELEMi ((size_t)32 * SEQi * Dhi)
#define POELEM ((size_t)32 * 16 * TMi * Dhi)   // partial O elems per half

__device__ __align__(16) __half gKh[NELEMi];
__device__ __align__(16) __half gVh[NELEMi];
__device__ __align__(16) float gPO[2][POELEM];
__device__ __align__(16) float gPL[2][32 * 16 * TMi];
__device__ int gCnt[512];                 // per-(bh,qt) arrival counter (self-resetting)

namespace {
constexpr int SM_BUF   = 2048;
constexpr int STAGEB   = 2 * TILEBi;
constexpr int SM_TOTAL = SM_BUF + 2 * STAGEB;   // 75776 B -> 3 CTAs/SM
constexpr float SCL = 0.18033688011112042f;     // log2(e)/8
constexpr float L2E = 1.4426950408889634f;
}

__device__ __forceinline__ uint32_t s2u(const void* p) {
    uint32_t a;
    asm("{ .reg .u64 t; cvta.to.shared.u64 t, %1; cvt.u32.u64 %0, t; }" : "=r"(a) : "l"(p));
    return a;
}
__device__ __forceinline__ void ldx4(uint32_t r[4], uint32_t a) {
    asm volatile("ldmatrix.sync.aligned.m8n8.x4.shared.b16 {%0,%1,%2,%3}, [%4];"
                 : "=r"(r[0]), "=r"(r[1]), "=r"(r[2]), "=r"(r[3]) : "r"(a));
}
__device__ __forceinline__ void ldx4t(uint32_t r[4], uint32_t a) {
    asm volatile("ldmatrix.sync.aligned.m8n8.x4.trans.shared.b16 {%0,%1,%2,%3}, [%4];"
                 : "=r"(r[0]), "=r"(r[1]), "=r"(r[2]), "=r"(r[3]) : "r"(a));
}
__device__ __forceinline__ void mma16816(float c[4], const uint32_t a[4],
                                         uint32_t b0, uint32_t b1) {
    asm("mma.sync.aligned.m16n8k16.row.col.f32.f16.f16.f32 "
        "{%0,%1,%2,%3}, {%4,%5,%6,%7}, {%8,%9}, {%0,%1,%2,%3};"
        : "+f"(c[0]), "+f"(c[1]), "+f"(c[2]), "+f"(c[3])
        : "r"(a[0]), "r"(a[1]), "r"(a[2]), "r"(a[3]), "r"(b0), "r"(b1));
}
__device__ __forceinline__ uint32_t pack2h(float a, float b) {
    uint32_t h;
    asm("cvt.rn.f16x2.f32 %0, %1, %2;" : "=r"(h) : "f"(b), "f"(a));
    return h;
}
__device__ __forceinline__ uint32_t h2ex2(uint32_t x) {
    uint32_t r;
    asm("ex2.approx.f16x2 %0, %1;" : "=r"(r) : "r"(x));
    return r;
}

// ---------------- pre-pass: fp32 K/V -> fp16 scratch ----------------
__global__ __launch_bounds__(256)
void conv_kernel(const float* __restrict__ K, const float* __restrict__ V)
{
    size_t base = (size_t)blockIdx.x * 1024 + threadIdx.x;   // float4 index
    const float* src = blockIdx.y ? V : K;
    __half* dst = blockIdx.y ? gVh : gKh;
    float4 x[4];
    #pragma unroll
    for (int i = 0; i < 4; i++) x[i] = __ldg((const float4*)src + base + i * 256);
    #pragma unroll
    for (int i = 0; i < 4; i++) {
        size_t e = base + i * 256;
        *(uint2*)(dst + e * 4) = make_uint2(pack2h(x[i].x, x[i].y), pack2h(x[i].z, x[i].w));
    }
}

__device__ __forceinline__ void prefetch_tile(uint32_t sdst, const __half* gsrc, int tid)
{
    #pragma unroll
    for (int j = 0; j < 8; j++) {
        int chunk = tid + j * 128;
        int row = chunk >> 3, c8 = chunk & 7;
        uint32_t d = sdst + (uint32_t)(row * ROWBi + c8 * 16);
        unsigned long long s =
            (unsigned long long)__cvta_generic_to_global(gsrc + (size_t)row * Dhi + c8 * 8);
        asm volatile("cp.async.cg.shared.global [%0], [%1], 16;" :: "r"(d), "l"(s));
    }
}

// ---- pipeline stages (R13, unchanged) ----
__device__ __forceinline__ void qk_block(const uint32_t qf[2][4][4], uint32_t sKh,
                                         int pair, int lid, float sraw[2][2][4])
{
    #pragma unroll
    for (int half = 0; half < 2; half++) {
        int key = pair * 16 + half * 8 + (lid & 7);
        uint32_t off = (uint32_t)(key * PADHi + ((lid >> 3) << 3)) * 2;
        uint32_t kh8[8];
        ldx4(&kh8[0], sKh + off);
        ldx4(&kh8[4], sKh + off + 64);
        #pragma unroll
        for (int rg = 0; rg < 2; rg++) {
            float acc[4] = {0.f, 0.f, 0.f, 0.f};
            #pragma unroll
            for (int j = 0; j < 4; j++)
                mma16816(acc, qf[rg][j], kh8[2 * j], kh8[2 * j + 1]);
            #pragma unroll
            for (int c = 0; c < 4; c++) sraw[rg][half][c] = acc[c];
        }
    }
}

__device__ __forceinline__ void softmax_pack(const float sraw[2][2][4],
                                             const float* biasT, int pair, int lid,
                                             uint32_t ap[2][4])
{
    #pragma unroll
    for (int half = 0; half < 2; half++) {
        float b0 = biasT[pair * 16 + half * 8 + 2 * (lid & 3)];
        float b1 = biasT[pair * 16 + half * 8 + 2 * (lid & 3) + 1];
        #pragma unroll
        for (int rg = 0; rg < 2; rg++) {
            float s0 = fmaf(sraw[rg][half][0], SCL, b0);
            float s1 = fmaf(sraw[rg][half][1], SCL, b1);
            float s2 = fmaf(sraw[rg][half][2], SCL, b0);
            float s3 = fmaf(sraw[rg][half][3], SCL, b1);
            ap[rg][half * 2]     = h2ex2(pack2h(s0, s1));
            ap[rg][half * 2 + 1] = h2ex2(pack2h(s2, s3));
        }
    }
}

__device__ __forceinline__ void pv_block(const uint32_t ap[2][4], uint32_t sVh,
                                         int pair, int lid, float o[2][8][4],
                                         float ox[2][4], uint32_t onesb)
{
    mma16816(ox[0], ap[0], onesb, onesb);
    mma16816(ox[1], ap[1], onesb, onesb);
    int keyr = pair * 16 + (lid & 15);
    #pragma unroll
    for (int np = 0; np < 4; np++) {
        uint32_t off = (uint32_t)(keyr * PADHi + np * 16 + ((lid >> 4) << 3)) * 2;
        uint32_t vh[4];
        ldx4t(vh, sVh + off);
        #pragma unroll
        for (int rg = 0; rg < 2; rg++) {
            mma16816(o[rg][2 * np],     ap[rg], vh[0], vh[1]);
            mma16816(o[rg][2 * np + 1], ap[rg], vh[2], vh[3]);
        }
    }
}

__global__ __launch_bounds__(128, 3)
void fa_hmma_kernel(const float* __restrict__ Q, const float* __restrict__ Mk,
                    float* __restrict__ O)
{
    extern __shared__ char sm[];
    float* biasB = (float*)sm;             // [2][128] floats; int slot at idx 300
    const uint32_t sb = s2u(sm);
    const uint32_t sK[2] = {sb + SM_BUF, sb + SM_BUF + STAGEB};
    const uint32_t sV[2] = {sK[0] + TILEBi, sK[1] + TILEBi};

    const int tid = threadIdx.x, wid = tid >> 5, lid = tid & 31;
    const int qt = blockIdx.x, bh = blockIdx.y, b = bh >> 4;
    const int kvh = blockIdx.z;

    const float* Qb = Q + ((size_t)bh * SEQi + (size_t)qt * TMi) * Dhi;
    const float* mb = Mk + (size_t)b * SEQi + (size_t)kvh * (NTH * TNi);
    const size_t kbase = (size_t)bh * SEQi * Dhi + (size_t)kvh * (NTH * TNi) * Dhi;

    const uint32_t onesb = (lid < 4) ? 0x3C003C00u : 0u;

    // ---- stage Q (fp32 -> fp16) through stage-0 K buffer ----
    #pragma unroll
    for (int v = 0; v < 16; v++) {
        int e = tid + v * 128;
        int r = e >> 4, c4 = e & 15;
        float4 q4 = __ldg((const float4*)(Qb + r * Dhi + c4 * 4));
        uint32_t byt = (uint32_t)(r * ROWBi + c4 * 8);
        *(uint2*)(sm + SM_BUF + byt) = make_uint2(pack2h(q4.x, q4.y), pack2h(q4.z, q4.w));
    }
    __syncthreads();

    uint32_t qf[2][4][4];
    #pragma unroll
    for (int rg = 0; rg < 2; rg++) {
        int qrow = wid * 32 + rg * 16 + (lid & 15);
        #pragma unroll
        for (int j = 0; j < 4; j++) {
            uint32_t off = (uint32_t)(qrow * PADHi + j * 16 + ((lid >> 4) << 3)) * 2;
            ldx4(qf[rg][j], sK[0] + off);
        }
    }
    __syncthreads();

    prefetch_tile(sK[0], gKh + kbase, tid);
    prefetch_tile(sV[0], gVh + kbase, tid);
    asm volatile("cp.async.commit_group;" ::: "memory");
    biasB[tid] = -1.0e6f * (1.0f - __ldg(&mb[tid])) * L2E;

    float o[2][8][4];
    float ox[2][4];
    #pragma unroll
    for (int rg = 0; rg < 2; rg++) {
        #pragma unroll
        for (int i = 0; i < 8; i++)
            #pragma unroll
            for (int j = 0; j < 4; j++) o[rg][i][j] = 0.0f;
        #pragma unroll
        for (int j = 0; j < 4; j++) ox[rg][j] = 0.0f;
    }

    for (int kt = 0; kt < NTH; kt++) {
        const int stg = kt & 1;
        asm volatile("cp.async.wait_group 0;" ::: "memory");
        __syncthreads();

        if (kt + 1 < NTH) {
            const size_t tb = kbase + (size_t)(kt + 1) * TNi * Dhi;
            prefetch_tile(sK[stg ^ 1], gKh + tb, tid);
            prefetch_tile(sV[stg ^ 1], gVh + tb, tid);
            asm volatile("cp.async.commit_group;" ::: "memory");
            biasB[(stg ^ 1) * 128 + tid] =
                -1.0e6f * (1.0f - __ldg(&mb[(kt + 1) * TNi + tid])) * L2E;
        }
        const uint32_t sKh = sK[stg], sVh = sV[stg];
        const float* biasT = biasB + stg * 128;

        uint32_t ap[2][4];
        {
            float sraw[2][2][4];
            qk_block(qf, sKh, 0, lid, sraw);
            softmax_pack(sraw, biasT, 0, lid, ap);
        }
        #pragma unroll
        for (int p = 0; p < 8; p++) {
            float sn[2][2][4];
            if (p < 7) qk_block(qf, sKh, p + 1, lid, sn);
            pv_block(ap, sVh, p, lid, o, ox, onesb);
            if (p < 7) softmax_pack(sn, biasT, p + 1, lid, ap);
        }
    }

    // ---- write UNNORMALIZED partial O + partial row sums ----
    const int uidx = bh * 16 + qt;
    float* pO = gPO[kvh] + (size_t)uidx * (TMi * Dhi);
    float* pL = gPL[kvh] + (size_t)uidx * TMi;
    #pragma unroll
    for (int rg = 0; rg < 2; rg++) {
        int row0 = wid * 32 + rg * 16 + (lid >> 2);
        int col  = 2 * (lid & 3);
        if ((lid & 3) == 0) {
            pL[row0]     = ox[rg][0];
            pL[row0 + 8] = ox[rg][2];
        }
        #pragma unroll
        for (int nt = 0; nt < 8; nt++) {
            int c = nt * 8 + col;
            *(float2*)(pO + (size_t)row0 * Dhi + c) =
                make_float2(o[rg][nt][0], o[rg][nt][1]);
            *(float2*)(pO + (size_t)(row0 + 8) * Dhi + c) =
                make_float2(o[rg][nt][2], o[rg][nt][3]);
        }
    }

    // ---- inline merge: second arriver combines both halves ----
    __threadfence();
    __syncthreads();
    volatile int* flag = (volatile int*)(sm) + 300;
    if (tid == 0) *flag = atomicAdd(&gCnt[uidx], 1);
    __syncthreads();
    if (*flag == 1) {
        // peer's partial is globally visible (it fenced before its atomic)
        const float* qO = gPO[kvh ^ 1] + (size_t)uidx * (TMi * Dhi);
        const float* l0 = gPL[0] + (size_t)uidx * TMi;
        const float* l1 = gPL[1] + (size_t)uidx * TMi;
        float* Ob = O + ((size_t)bh * SEQi + (size_t)qt * TMi) * Dhi;
        #pragma unroll
        for (int rg = 0; rg < 2; rg++) {
            int row0 = wid * 32 + rg * 16 + (lid >> 2);
            int col  = 2 * (lid & 3);
            // fixed-order sums (kvh0 + kvh1) -> deterministic bits
            float inv0 = 1.0f / (__ldg(&l0[row0])     + __ldg(&l1[row0]));
            float inv1 = 1.0f / (__ldg(&l0[row0 + 8]) + __ldg(&l1[row0 + 8]));
            #pragma unroll
            for (int nt = 0; nt < 8; nt++) {
                int c = nt * 8 + col;
                float2 pa = __ldg((const float2*)(qO + (size_t)row0 * Dhi + c));
                float2 pb = __ldg((const float2*)(qO + (size_t)(row0 + 8) * Dhi + c));
                float s0, s1, s2, s3;
                if (kvh == 0) {          // own is kvh0: own + peer
                    s0 = o[rg][nt][0] + pa.x;  s1 = o[rg][nt][1] + pa.y;
                    s2 = o[rg][nt][2] + pb.x;  s3 = o[rg][nt][3] + pb.y;
                } else {                 // own is kvh1: peer + own
                    s0 = pa.x + o[rg][nt][0];  s1 = pa.y + o[rg][nt][1];
                    s2 = pb.x + o[rg][nt][2];  s3 = pb.y + o[rg][nt][3];
                }
                *(float2*)(Ob + (size_t)row0 * Dhi + c)       = make_float2(s0 * inv0, s1 * inv0);
                *(float2*)(Ob + (size_t)(row0 + 8) * Dhi + c) = make_float2(s2 * inv1, s3 * inv1);
            }
        }
        if (tid == 0) gCnt[uidx] = 0;    // self-reset for graph replay
    }
}

extern "C" void kernel_launch(void* const* d_in, const int* in_sizes, int n_in,
                              void* d_out, int out_size)
{
    const float* Q = (const float*)d_in[0];
    const float* K = (const float*)d_in[1];
    const float* V = (const float*)d_in[2];
    const float* M = (const float*)d_in[3];
    float* O = (float*)d_out;

    conv_kernel<<<dim3(1024, 2), 256>>>(K, V);

    cudaFuncSetAttribute(fa_hmma_kernel,
                         cudaFuncAttributeMaxDynamicSharedMemorySize, SM_TOTAL);
    dim3 grid(16, 32, 2);   // qt x bh x kv-half
    fa_hmma_kernel<<<grid, 128, SM_TOTAL>>>(Q, M, O);
}

// round 17
// speedup vs baseline: 1.1315x; 1.0269x over previous
#include <cuda_runtime.h>
#include <cuda_fp16.h>
#include <cstdint>

// SoftmaxSelfAttention B=2,H=16,S=2048,D=64 fp32.
// Round 17: R16 (inline merge) + Q pre-converted to fp16 in the conv
// pre-pass. Main-kernel prologue is now a single cp.async group (Q tile
// staged into stage-1 K buffer + K/V tile 0) -> wait -> ldmatrix. Removes
// the serial fp32-LDG/cvt/STS Q chain per wave and halves Q DRAM traffic.

#define SEQi  2048
#define Dhi   64
#define TMi   128
#define TNi   128
#define NTH   8                           // tiles per kv half
#define PADHi 72
#define ROWBi 144
#define TILEBi (TNi * ROWBi)              // 18432 B
#define NELEMi ((size_t)32 * SEQi * Dhi)
#define POELEM ((size_t)32 * 16 * TMi * Dhi)   // partial O elems per half

__device__ __align__(16) __half gKh[NELEMi];
__device__ __align__(16) __half gVh[NELEMi];
__device__ __align__(16) __half gQh[NELEMi];
__device__ __align__(16) float gPO[2][POELEM];
__device__ __align__(16) float gPL[2][32 * 16 * TMi];
__device__ int gCnt[512];                 // per-(bh,qt) arrival counter (self-resetting)

namespace {
constexpr int SM_BUF   = 2048;
constexpr int STAGEB   = 2 * TILEBi;
constexpr int SM_TOTAL = SM_BUF + 2 * STAGEB;   // 75776 B -> 3 CTAs/SM
constexpr float SCL = 0.18033688011112042f;     // log2(e)/8
constexpr float L2E = 1.4426950408889634f;
}

__device__ __forceinline__ uint32_t s2u(const void* p) {
    uint32_t a;
    asm("{ .reg .u64 t; cvta.to.shared.u64 t, %1; cvt.u32.u64 %0, t; }" : "=r"(a) : "l"(p));
    return a;
}
__device__ __forceinline__ void ldx4(uint32_t r[4], uint32_t a) {
    asm volatile("ldmatrix.sync.aligned.m8n8.x4.shared.b16 {%0,%1,%2,%3}, [%4];"
                 : "=r"(r[0]), "=r"(r[1]), "=r"(r[2]), "=r"(r[3]) : "r"(a));
}
__device__ __forceinline__ void ldx4t(uint32_t r[4], uint32_t a) {
    asm volatile("ldmatrix.sync.aligned.m8n8.x4.trans.shared.b16 {%0,%1,%2,%3}, [%4];"
                 : "=r"(r[0]), "=r"(r[1]), "=r"(r[2]), "=r"(r[3]) : "r"(a));
}
__device__ __forceinline__ void mma16816(float c[4], const uint32_t a[4],
                                         uint32_t b0, uint32_t b1) {
    asm("mma.sync.aligned.m16n8k16.row.col.f32.f16.f16.f32 "
        "{%0,%1,%2,%3}, {%4,%5,%6,%7}, {%8,%9}, {%0,%1,%2,%3};"
        : "+f"(c[0]), "+f"(c[1]), "+f"(c[2]), "+f"(c[3])
        : "r"(a[0]), "r"(a[1]), "r"(a[2]), "r"(a[3]), "r"(b0), "r"(b1));
}
__device__ __forceinline__ uint32_t pack2h(float a, float b) {
    uint32_t h;
    asm("cvt.rn.f16x2.f32 %0, %1, %2;" : "=r"(h) : "f"(b), "f"(a));
    return h;
}
__device__ __forceinline__ uint32_t h2ex2(uint32_t x) {
    uint32_t r;
    asm("ex2.approx.f16x2 %0, %1;" : "=r"(r) : "r"(x));
    return r;
}

// ---------------- pre-pass: fp32 Q/K/V -> fp16 scratch ----------------
__global__ __launch_bounds__(256)
void conv_kernel(const float* __restrict__ Q, const float* __restrict__ K,
                 const float* __restrict__ V)
{
    size_t base = (size_t)blockIdx.x * 1024 + threadIdx.x;   // float4 index
    const float* src = (blockIdx.y == 0) ? K : (blockIdx.y == 1) ? V : Q;
    __half* dst = (blockIdx.y == 0) ? gKh : (blockIdx.y == 1) ? gVh : gQh;
    float4 x[4];
    #pragma unroll
    for (int i = 0; i < 4; i++) x[i] = __ldg((const float4*)src + base + i * 256);
    #pragma unroll
    for (int i = 0; i < 4; i++) {
        size_t e = base + i * 256;
        *(uint2*)(dst + e * 4) = make_uint2(pack2h(x[i].x, x[i].y), pack2h(x[i].z, x[i].w));
    }
}

__device__ __forceinline__ void prefetch_tile(uint32_t sdst, const __half* gsrc, int tid)
{
    #pragma unroll
    for (int j = 0; j < 8; j++) {
        int chunk = tid + j * 128;
        int row = chunk >> 3, c8 = chunk & 7;
        uint32_t d = sdst + (uint32_t)(row * ROWBi + c8 * 16);
        unsigned long long s =
            (unsigned long long)__cvta_generic_to_global(gsrc + (size_t)row * Dhi + c8 * 8);
        asm volatile("cp.async.cg.shared.global [%0], [%1], 16;" :: "r"(d), "l"(s));
    }
}

// ---- pipeline stages (R13, unchanged) ----
__device__ __forceinline__ void qk_block(const uint32_t qf[2][4][4], uint32_t sKh,
                                         int pair, int lid, float sraw[2][2][4])
{
    #pragma unroll
    for (int half = 0; half < 2; half++) {
        int key = pair * 16 + half * 8 + (lid & 7);
        uint32_t off = (uint32_t)(key * PADHi + ((lid >> 3) << 3)) * 2;
        uint32_t kh8[8];
        ldx4(&kh8[0], sKh + off);
        ldx4(&kh8[4], sKh + off + 64);
        #pragma unroll
        for (int rg = 0; rg < 2; rg++) {
            float acc[4] = {0.f, 0.f, 0.f, 0.f};
            #pragma unroll
            for (int j = 0; j < 4; j++)
                mma16816(acc, qf[rg][j], kh8[2 * j], kh8[2 * j + 1]);
            #pragma unroll
            for (int c = 0; c < 4; c++) sraw[rg][half][c] = acc[c];
        }
    }
}

__device__ __forceinline__ void softmax_pack(const float sraw[2][2][4],
                                             const float* biasT, int pair, int lid,
                                             uint32_t ap[2][4])
{
    #pragma unroll
    for (int half = 0; half < 2; half++) {
        float b0 = biasT[pair * 16 + half * 8 + 2 * (lid & 3)];
        float b1 = biasT[pair * 16 + half * 8 + 2 * (lid & 3) + 1];
        #pragma unroll
        for (int rg = 0; rg < 2; rg++) {
            float s0 = fmaf(sraw[rg][half][0], SCL, b0);
            float s1 = fmaf(sraw[rg][half][1], SCL, b1);
            float s2 = fmaf(sraw[rg][half][2], SCL, b0);
            float s3 = fmaf(sraw[rg][half][3], SCL, b1);
            ap[rg][half * 2]     = h2ex2(pack2h(s0, s1));
            ap[rg][half * 2 + 1] = h2ex2(pack2h(s2, s3));
        }
    }
}

__device__ __forceinline__ void pv_block(const uint32_t ap[2][4], uint32_t sVh,
                                         int pair, int lid, float o[2][8][4],
                                         float ox[2][4], uint32_t onesb)
{
    mma16816(ox[0], ap[0], onesb, onesb);
    mma16816(ox[1], ap[1], onesb, onesb);
    int keyr = pair * 16 + (lid & 15);
    #pragma unroll
    for (int np = 0; np < 4; np++) {
        uint32_t off = (uint32_t)(keyr * PADHi + np * 16 + ((lid >> 4) << 3)) * 2;
        uint32_t vh[4];
        ldx4t(vh, sVh + off);
        #pragma unroll
        for (int rg = 0; rg < 2; rg++) {
            mma16816(o[rg][2 * np],     ap[rg], vh[0], vh[1]);
            mma16816(o[rg][2 * np + 1], ap[rg], vh[2], vh[3]);
        }
    }
}

__global__ __launch_bounds__(128, 3)
void fa_hmma_kernel(const float* __restrict__ Mk, float* __restrict__ O)
{
    extern __shared__ char sm[];
    float* biasB = (float*)sm;             // [2][128] floats; int flag at idx 300
    const uint32_t sb = s2u(sm);
    const uint32_t sK[2] = {sb + SM_BUF, sb + SM_BUF + STAGEB};
    const uint32_t sV[2] = {sK[0] + TILEBi, sK[1] + TILEBi};

    const int tid = threadIdx.x, wid = tid >> 5, lid = tid & 31;
    const int qt = blockIdx.x, bh = blockIdx.y, b = bh >> 4;
    const int kvh = blockIdx.z;

    const float* mb = Mk + (size_t)b * SEQi + (size_t)kvh * (NTH * TNi);
    const size_t qbase = (size_t)bh * SEQi * Dhi + (size_t)qt * TMi * Dhi;
    const size_t kbase = (size_t)bh * SEQi * Dhi + (size_t)kvh * (NTH * TNi) * Dhi;

    const uint32_t onesb = (lid < 4) ? 0x3C003C00u : 0u;

    // ---- single cp.async prologue: Q tile (staged in stage-1 K buffer)
    //      + K/V tile 0 into stage 0 ----
    prefetch_tile(sK[1], gQh + qbase, tid);
    prefetch_tile(sK[0], gKh + kbase, tid);
    prefetch_tile(sV[0], gVh + kbase, tid);
    asm volatile("cp.async.commit_group;" ::: "memory");
    biasB[tid] = -1.0e6f * (1.0f - __ldg(&mb[tid])) * L2E;

    asm volatile("cp.async.wait_group 0;" ::: "memory");
    __syncthreads();

    uint32_t qf[2][4][4];
    #pragma unroll
    for (int rg = 0; rg < 2; rg++) {
        int qrow = wid * 32 + rg * 16 + (lid & 15);
        #pragma unroll
        for (int j = 0; j < 4; j++) {
            uint32_t off = (uint32_t)(qrow * PADHi + j * 16 + ((lid >> 4) << 3)) * 2;
            ldx4(qf[rg][j], sK[1] + off);
        }
    }
    // loop-top __syncthreads at kt=0 orders these LDSMs before the tile-1
    // prefetch that overwrites the Q staging area.

    float o[2][8][4];
    float ox[2][4];
    #pragma unroll
    for (int rg = 0; rg < 2; rg++) {
        #pragma unroll
        for (int i = 0; i < 8; i++)
            #pragma unroll
            for (int j = 0; j < 4; j++) o[rg][i][j] = 0.0f;
        #pragma unroll
        for (int j = 0; j < 4; j++) ox[rg][j] = 0.0f;
    }

    for (int kt = 0; kt < NTH; kt++) {
        const int stg = kt & 1;
        asm volatile("cp.async.wait_group 0;" ::: "memory");
        __syncthreads();

        if (kt + 1 < NTH) {
            const size_t tb = kbase + (size_t)(kt + 1) * TNi * Dhi;
            prefetch_tile(sK[stg ^ 1], gKh + tb, tid);
            prefetch_tile(sV[stg ^ 1], gVh + tb, tid);
            asm volatile("cp.async.commit_group;" ::: "memory");
            biasB[(stg ^ 1) * 128 + tid] =
                -1.0e6f * (1.0f - __ldg(&mb[(kt + 1) * TNi + tid])) * L2E;
        }
        const uint32_t sKh = sK[stg], sVh = sV[stg];
        const float* biasT = biasB + stg * 128;

        uint32_t ap[2][4];
        {
            float sraw[2][2][4];
            qk_block(qf, sKh, 0, lid, sraw);
            softmax_pack(sraw, biasT, 0, lid, ap);
        }
        #pragma unroll
        for (int p = 0; p < 8; p++) {
            float sn[2][2][4];
            if (p < 7) qk_block(qf, sKh, p + 1, lid, sn);
            pv_block(ap, sVh, p, lid, o, ox, onesb);
            if (p < 7) softmax_pack(sn, biasT, p + 1, lid, ap);
        }
    }

    // ---- write UNNORMALIZED partial O + partial row sums ----
    const int uidx = bh * 16 + qt;
    float* pO = gPO[kvh] + (size_t)uidx * (TMi * Dhi);
    float* pL = gPL[kvh] + (size_t)uidx * TMi;
    #pragma unroll
    for (int rg = 0; rg < 2; rg++) {
        int row0 = wid * 32 + rg * 16 + (lid >> 2);
        int col  = 2 * (lid & 3);
        if ((lid & 3) == 0) {
            pL[row0]     = ox[rg][0];
            pL[row0 + 8] = ox[rg][2];
        }
        #pragma unroll
        for (int nt = 0; nt < 8; nt++) {
            int c = nt * 8 + col;
            *(float2*)(pO + (size_t)row0 * Dhi + c) =
                make_float2(o[rg][nt][0], o[rg][nt][1]);
            *(float2*)(pO + (size_t)(row0 + 8) * Dhi + c) =
                make_float2(o[rg][nt][2], o[rg][nt][3]);
        }
    }

    // ---- inline merge: second arriver combines both halves ----
    __threadfence();
    __syncthreads();
    volatile int* flag = (volatile int*)(sm) + 300;
    if (tid == 0) *flag = atomicAdd(&gCnt[uidx], 1);
    __syncthreads();
    if (*flag == 1) {
        const float* qO = gPO[kvh ^ 1] + (size_t)uidx * (TMi * Dhi);
        const float* l0 = gPL[0] + (size_t)uidx * TMi;
        const float* l1 = gPL[1] + (size_t)uidx * TMi;
        float* Ob = O + ((size_t)bh * SEQi + (size_t)qt * TMi) * Dhi;
        #pragma unroll
        for (int rg = 0; rg < 2; rg++) {
            int row0 = wid * 32 + rg * 16 + (lid >> 2);
            int col  = 2 * (lid & 3);
            float inv0 = 1.0f / (__ldg(&l0[row0])     + __ldg(&l1[row0]));
            float inv1 = 1.0f / (__ldg(&l0[row0 + 8]) + __ldg(&l1[row0 + 8]));
            #pragma unroll
            for (int nt = 0; nt < 8; nt++) {
                int c = nt * 8 + col;
                float2 pa = __ldg((const float2*)(qO + (size_t)row0 * Dhi + c));
                float2 pb = __ldg((const float2*)(qO + (size_t)(row0 + 8) * Dhi + c));
                float s0, s1, s2, s3;
                if (kvh == 0) {
                    s0 = o[rg][nt][0] + pa.x;  s1 = o[rg][nt][1] + pa.y;
                    s2 = o[rg][nt][2] + pb.x;  s3 = o[rg][nt][3] + pb.y;
                } else {
                    s0 = pa.x + o[rg][nt][0];  s1 = pa.y + o[rg][nt][1];
                    s2 = pb.x + o[rg][nt][2];  s3 = pb.y + o[rg][nt][3];
                }
                *(float2*)(Ob + (size_t)row0 * Dhi + c)       = make_float2(s0 * inv0, s1 * inv0);
                *(float2*)(Ob + (size_t)(row0 + 8) * Dhi + c) = make_float2(s2 * inv1, s3 * inv1);
            }
        }
        if (tid == 0) gCnt[uidx] = 0;
    }
}

extern "C" void kernel_launch(void* const* d_in, const int* in_sizes, int n_in,
                              void* d_out, int out_size)
{
    const float* Q = (const float*)d_in[0];
    const float* K = (const float*)d_in[1];
    const float* V = (const float*)d_in[2];
    const float* M = (const float*)d_in[3];
    float* O = (float*)d_out;

    conv_kernel<<<dim3(1024, 3), 256>>>(Q, K, V);

    cudaFuncSetAttribute(fa_hmma_kernel,
                         cudaFuncAttributeMaxDynamicSharedMemorySize, SM_TOTAL);
    dim3 grid(16, 32, 2);   // qt x bh x kv-half
    fa_hmma_kernel<<<grid, 128, SM_TOTAL>>>(M, O);
}